// round 1
// baseline (speedup 1.0000x reference)
#include <cuda_runtime.h>

// ---------------------------------------------------------------------------
// Net_16673063043559: 2-layer dense GCN on GB300
//   h   = emb[x]
//   L1:  msg = relu(h @ w1^T + b1);  h1 = Dr^-1/2 (m @ (Dc^-1/2 msg))
//   L2:  msg = relu(h1 @ w2^T + b2); h2 = Dr^-1/2 (m @ (Dc^-1/2 msg))
//   pooled = segment_max(h2, 128-row segments); logits = pooled @ wc^T + bc
// Big GEMMs use mma.sync tf32 (rna-rounded), fp32 accumulation.
// ---------------------------------------------------------------------------

#define NN     8192
#define FDIM   128
#define NGRAPH 64
#define NCLS   16

// Scratch (device globals: no allocation allowed)
__device__ float g_msg[NN * FDIM];     // scaled message buffer (both layers)
__device__ float g_h[NN * FDIM];       // propagate output (both layers)
__device__ float g_rowdeg[NN];
__device__ float g_coldeg[NN];

// ---------------------------------------------------------------------------
__device__ __forceinline__ float to_tf32(float x) {
    unsigned int u;
    asm("cvt.rna.tf32.f32 %0, %1;" : "=r"(u) : "f"(x));
    return __uint_as_float(u);
}

__device__ __forceinline__ void mma_tf32(float (&c)[4],
                                         unsigned a0, unsigned a1, unsigned a2, unsigned a3,
                                         unsigned b0, unsigned b1) {
    asm volatile(
        "mma.sync.aligned.m16n8k8.row.col.f32.tf32.tf32.f32 "
        "{%0,%1,%2,%3}, {%4,%5,%6,%7}, {%8,%9}, {%0,%1,%2,%3};"
        : "+f"(c[0]), "+f"(c[1]), "+f"(c[2]), "+f"(c[3])
        : "r"(a0), "r"(a1), "r"(a2), "r"(a3), "r"(b0), "r"(b1));
}

// ---------------------------------------------------------------------------
// Zero degree accumulators (needed every replay: atomics accumulate)
__global__ void zero_deg_kernel() {
    int i = blockIdx.x * blockDim.x + threadIdx.x;
    if (i < NN) { g_rowdeg[i] = 0.f; g_coldeg[i] = 0.f; }
}

// ---------------------------------------------------------------------------
// One pass over m: row sums and col sums.
// Grid (32, 16): block = 256 cols x 512 rows. Thread owns one column.
__global__ __launch_bounds__(256) void deg_kernel(const float* __restrict__ m) {
    const int c    = blockIdx.x * 256 + threadIdx.x;
    const int r0   = blockIdx.y * 512;
    const int lane = threadIdx.x & 31;
    float colacc = 0.f;

    for (int r = r0; r < r0 + 512; r += 8) {
        float v[8];
#pragma unroll
        for (int j = 0; j < 8; j++)
            v[j] = m[(size_t)(r + j) * NN + c];
#pragma unroll
        for (int j = 0; j < 8; j++) colacc += v[j];
        // 8 interleaved warp reductions (hide shuffle latency)
#pragma unroll
        for (int j = 0; j < 8; j++) {
            v[j] += __shfl_xor_sync(0xffffffffu, v[j], 16);
            v[j] += __shfl_xor_sync(0xffffffffu, v[j], 8);
            v[j] += __shfl_xor_sync(0xffffffffu, v[j], 4);
            v[j] += __shfl_xor_sync(0xffffffffu, v[j], 2);
            v[j] += __shfl_xor_sync(0xffffffffu, v[j], 1);
        }
        if (lane == 0) {
#pragma unroll
            for (int j = 0; j < 8; j++)
                atomicAdd(&g_rowdeg[r + j], v[j]);
        }
    }
    atomicAdd(&g_coldeg[c], colacc);
}

// ---------------------------------------------------------------------------
// msgS = relu(in @ w^T + b) * rsqrt(col_deg[row]),  in is either gather(emb, x)
// (gather=1) or g_h (gather=0). Writes g_msg. Block = 32 rows, 256 threads,
// thread computes 4 rows x 4 cols. k staged in 32-chunks.
__global__ __launch_bounds__(256) void linear_kernel(
    const float* __restrict__ ext, const int* __restrict__ idx,
    const float* __restrict__ w, const float* __restrict__ b, int gather) {
    __shared__ float ht[32 * 36];    // [row][k] padded
    __shared__ float wt[32 * 132];   // [k][col] padded (transposed w chunk)

    const int tid  = threadIdx.x;
    const int brow = blockIdx.x * 32;
    const int rg   = tid >> 5;       // warp id = row group (all lanes same rows)
    const int cg   = tid & 31;

    // staging assignment: thread loads one float4 of its input row per chunk
    const int sr  = tid >> 3;            // 0..31 row
    const int sk4 = (tid & 7) << 2;      // 0..28 k offset
    const int node = brow + sr;
    const float* src;
    if (gather) src = ext + (size_t)idx[node] * FDIM;
    else        src = &g_h[(size_t)node * FDIM];

    float acc[4][4];
#pragma unroll
    for (int j = 0; j < 4; j++)
#pragma unroll
        for (int jj = 0; jj < 4; jj++) acc[j][jj] = 0.f;

    for (int kc = 0; kc < 4; kc++) {
        const int k0 = kc * 32;
        if (kc) __syncthreads();   // previous chunk fully consumed

        float4 hv = *(const float4*)(src + k0 + sk4);
        ht[sr * 36 + sk4 + 0] = hv.x;
        ht[sr * 36 + sk4 + 1] = hv.y;
        ht[sr * 36 + sk4 + 2] = hv.z;
        ht[sr * 36 + sk4 + 3] = hv.w;

#pragma unroll
        for (int i = 0; i < 4; i++) {
            int lin4 = tid + i * 256;        // 0..1023 float4 slots
            int c    = lin4 >> 3;            // 0..127 output col
            int kk4  = (lin4 & 7) << 2;      // 0..28
            float4 wv = *(const float4*)(w + (size_t)c * FDIM + k0 + kk4);
            wt[(kk4 + 0) * 132 + c] = wv.x;
            wt[(kk4 + 1) * 132 + c] = wv.y;
            wt[(kk4 + 2) * 132 + c] = wv.z;
            wt[(kk4 + 3) * 132 + c] = wv.w;
        }
        __syncthreads();

#pragma unroll
        for (int k = 0; k < 32; k++) {
            float hvv[4], wvv[4];
#pragma unroll
            for (int j = 0; j < 4; j++)  hvv[j]  = ht[(rg * 4 + j) * 36 + k];
#pragma unroll
            for (int jj = 0; jj < 4; jj++) wvv[jj] = wt[k * 132 + cg + 32 * jj];
#pragma unroll
            for (int j = 0; j < 4; j++)
#pragma unroll
                for (int jj = 0; jj < 4; jj++)
                    acc[j][jj] += hvv[j] * wvv[jj];
        }
    }

#pragma unroll
    for (int j = 0; j < 4; j++) {
        const int rr = brow + rg * 4 + j;
        const float sc = rsqrtf(g_coldeg[rr]);
#pragma unroll
        for (int jj = 0; jj < 4; jj++) {
            const int c = cg + 32 * jj;
            float v = acc[j][jj] + b[c];
            v = fmaxf(v, 0.f);
            g_msg[(size_t)rr * FDIM + c] = v * sc;
        }
    }
}

// ---------------------------------------------------------------------------
// g_h = rsqrt(row_deg) * (m @ g_msg)   -- M=8192, N=128, K=8192, tf32 mma.
// Block tile 32x128, BK=32, double-buffered smem, 256 threads (8 warps 2x4),
// warp tile 16x32 (4 x m16n8k8 accumulators).
__global__ __launch_bounds__(256) void gemm_kernel(const float* __restrict__ A) {
    __shared__ float As[2][32 * 36];   // [row][k] padded, tf32-rounded
    __shared__ float Bs[2][32 * 132];  // [k][col] padded, tf32-rounded

    const int tid  = threadIdx.x;
    const int brow = blockIdx.x * 32;
    const int warp = tid >> 5, lane = tid & 31;
    const int g    = lane >> 2, tg = lane & 3;
    const int wr   = (warp >> 2) * 16;   // 0 or 16
    const int wcn  = (warp & 3) * 32;    // 0,32,64,96

    // A staging: thread -> (row, 4 cols)
    const int ar = tid >> 3;
    const int ac = (tid & 7) << 2;
    const float* Aop = A + (size_t)(brow + ar) * NN + ac;

    float acc[4][4];
#pragma unroll
    for (int nt = 0; nt < 4; nt++)
#pragma unroll
        for (int e = 0; e < 4; e++) acc[nt][e] = 0.f;

    // initial tile
    {
        float4 ra = *(const float4*)Aop;
        As[0][ar * 36 + ac + 0] = to_tf32(ra.x);
        As[0][ar * 36 + ac + 1] = to_tf32(ra.y);
        As[0][ar * 36 + ac + 2] = to_tf32(ra.z);
        As[0][ar * 36 + ac + 3] = to_tf32(ra.w);
#pragma unroll
        for (int i = 0; i < 4; i++) {
            int lin = tid + i * 256;
            int br  = lin >> 5, bc4 = (lin & 31) << 2;
            float4 rb = *(const float4*)(&g_msg[(size_t)br * FDIM + bc4]);
            Bs[0][br * 132 + bc4 + 0] = to_tf32(rb.x);
            Bs[0][br * 132 + bc4 + 1] = to_tf32(rb.y);
            Bs[0][br * 132 + bc4 + 2] = to_tf32(rb.z);
            Bs[0][br * 132 + bc4 + 3] = to_tf32(rb.w);
        }
    }
    __syncthreads();

    int cur = 0;
#pragma unroll 1
    for (int kt = 0; kt < NN / 32; kt++) {
        float4 ra;
        float4 rb[4];
        const bool has_next = (kt + 1) < (NN / 32);
        if (has_next) {
            const int k0n = (kt + 1) * 32;
            ra = *(const float4*)(Aop + k0n);
#pragma unroll
            for (int i = 0; i < 4; i++) {
                int lin = tid + i * 256;
                int br  = lin >> 5, bc4 = (lin & 31) << 2;
                rb[i] = *(const float4*)(&g_msg[(size_t)(k0n + br) * FDIM + bc4]);
            }
        }

        const float* A_ = As[cur];
        const float* B_ = Bs[cur];
#pragma unroll
        for (int kk = 0; kk < 32; kk += 8) {
            unsigned a0 = __float_as_uint(A_[(wr + g)     * 36 + kk + tg]);
            unsigned a1 = __float_as_uint(A_[(wr + g + 8) * 36 + kk + tg]);
            unsigned a2 = __float_as_uint(A_[(wr + g)     * 36 + kk + tg + 4]);
            unsigned a3 = __float_as_uint(A_[(wr + g + 8) * 36 + kk + tg + 4]);
#pragma unroll
            for (int nt = 0; nt < 4; nt++) {
                unsigned b0 = __float_as_uint(B_[(kk + tg)     * 132 + wcn + nt * 8 + g]);
                unsigned b1 = __float_as_uint(B_[(kk + tg + 4) * 132 + wcn + nt * 8 + g]);
                mma_tf32(acc[nt], a0, a1, a2, a3, b0, b1);
            }
        }

        if (has_next) {
            const int nxt = cur ^ 1;
            As[nxt][ar * 36 + ac + 0] = to_tf32(ra.x);
            As[nxt][ar * 36 + ac + 1] = to_tf32(ra.y);
            As[nxt][ar * 36 + ac + 2] = to_tf32(ra.z);
            As[nxt][ar * 36 + ac + 3] = to_tf32(ra.w);
#pragma unroll
            for (int i = 0; i < 4; i++) {
                int lin = tid + i * 256;
                int br  = lin >> 5, bc4 = (lin & 31) << 2;
                Bs[nxt][br * 132 + bc4 + 0] = to_tf32(rb[i].x);
                Bs[nxt][br * 132 + bc4 + 1] = to_tf32(rb[i].y);
                Bs[nxt][br * 132 + bc4 + 2] = to_tf32(rb[i].z);
                Bs[nxt][br * 132 + bc4 + 3] = to_tf32(rb[i].w);
            }
            __syncthreads();
            cur = nxt;
        }
    }

    // epilogue: scale by rsqrt(row_deg)
    const float rs0 = rsqrtf(g_rowdeg[brow + wr + g]);
    const float rs1 = rsqrtf(g_rowdeg[brow + wr + g + 8]);
#pragma unroll
    for (int nt = 0; nt < 4; nt++) {
        const int col = wcn + nt * 8 + 2 * tg;
        const size_t o0 = (size_t)(brow + wr + g)     * FDIM + col;
        const size_t o1 = (size_t)(brow + wr + g + 8) * FDIM + col;
        g_h[o0]     = acc[nt][0] * rs0;
        g_h[o0 + 1] = acc[nt][1] * rs0;
        g_h[o1]     = acc[nt][2] * rs1;
        g_h[o1 + 1] = acc[nt][3] * rs1;
    }
}

// ---------------------------------------------------------------------------
// pooled[g] = max over 128 contiguous rows of g_h; logits = pooled @ wc^T + bc
__global__ void pool_classify_kernel(const float* __restrict__ wc,
                                     const float* __restrict__ bc,
                                     float* __restrict__ out) {
    __shared__ float pooled[FDIM];
    const int gidx = blockIdx.x;
    const int c    = threadIdx.x;
    const float* base = &g_h[(size_t)gidx * 128 * FDIM + c];
    float mx = -1e30f;
#pragma unroll 8
    for (int r = 0; r < 128; r++)
        mx = fmaxf(mx, base[(size_t)r * FDIM]);
    pooled[c] = mx;
    __syncthreads();
    if (c < NCLS) {
        float a = bc[c];
#pragma unroll 8
        for (int k = 0; k < FDIM; k++)
            a += pooled[k] * wc[c * FDIM + k];
        out[gidx * NCLS + c] = a;
    }
}

// ---------------------------------------------------------------------------
extern "C" void kernel_launch(void* const* d_in, const int* in_sizes, int n_in,
                              void* d_out, int out_size) {
    const int*   x   = (const int*)d_in[0];
    const float* m   = (const float*)d_in[1];
    // d_in[2] = bm (unused: segments are exactly contiguous 128-row blocks)
    const float* emb = (const float*)d_in[3];
    const float* w1  = (const float*)d_in[4];
    const float* b1  = (const float*)d_in[5];
    const float* w2  = (const float*)d_in[6];
    const float* b2  = (const float*)d_in[7];
    const float* wc  = (const float*)d_in[8];
    const float* bc  = (const float*)d_in[9];
    float* out = (float*)d_out;

    zero_deg_kernel<<<32, 256>>>();
    deg_kernel<<<dim3(32, 16), 256>>>(m);

    // layer 1
    linear_kernel<<<NN / 32, 256>>>(emb, x, w1, b1, 1);
    gemm_kernel<<<NN / 32, 256>>>(m);
    // layer 2
    linear_kernel<<<NN / 32, 256>>>(nullptr, nullptr, w2, b2, 0);
    gemm_kernel<<<NN / 32, 256>>>(m);

    pool_classify_kernel<<<NGRAPH, FDIM>>>(wc, bc, out);
}

// round 2
// speedup vs baseline: 1.9791x; 1.9791x over previous
#include <cuda_runtime.h>
#include <cuda_fp16.h>

// ---------------------------------------------------------------------------
// Net_16673063043559: 2-layer dense GCN on GB300 (sm_103a)
//   deg pass: row/col sums of m + fp16 conversion of m (one read of m)
//   L1:  msg = relu(h @ w1^T + b1) * rsqrt(coldeg);  h1 = rsqrt(rowdeg)*(m @ msg)
//   L2:  same with w2/b2
//   pooled = segment_max over contiguous 128-row blocks; logits = pooled@wc^T+bc
// Propagate GEMMs: fp16 HMMA (m16n8k16), fp32 accumulate, ldmatrix + cp.async.
// ---------------------------------------------------------------------------

#define NN     8192
#define FDIM   128
#define NGRAPH 64
#define NCLS   16

// GEMM tiling
#define BM     64
#define BK     32
#define APAD   40     // halves per A smem row (80B stride, 16B-aligned, bank-rotating)
#define BPAD   136    // halves per B smem row (272B stride)
#define NSTAGE 3
#define KTILES (NN / BK)

// Scratch (device globals: no allocation allowed)
__device__ __half g_mh[(size_t)NN * NN];   // fp16 copy of m (128 MB)
__device__ __half g_msg[NN * FDIM];        // scaled message (fp16, GEMM B operand)
__device__ float  g_h[NN * FDIM];          // propagate output (fp32)
__device__ float  g_rowdeg[NN];
__device__ float  g_coldeg[NN];

// ---------------------------------------------------------------------------
__device__ __forceinline__ unsigned smem_u32(const void* p) {
    return (unsigned)__cvta_generic_to_shared(p);
}

__device__ __forceinline__ void cp_async16(unsigned s, const void* g) {
    asm volatile("cp.async.cg.shared.global [%0], [%1], 16;\n" :: "r"(s), "l"(g));
}
__device__ __forceinline__ void cp_commit() {
    asm volatile("cp.async.commit_group;\n");
}
template <int N>
__device__ __forceinline__ void cp_wait() {
    asm volatile("cp.async.wait_group %0;\n" :: "n"(N));
}

__device__ __forceinline__ void ldsm4(unsigned r[4], unsigned a) {
    asm volatile("ldmatrix.sync.aligned.m8n8.x4.shared.b16 {%0,%1,%2,%3}, [%4];"
                 : "=r"(r[0]), "=r"(r[1]), "=r"(r[2]), "=r"(r[3]) : "r"(a));
}
__device__ __forceinline__ void ldsm4t(unsigned r[4], unsigned a) {
    asm volatile("ldmatrix.sync.aligned.m8n8.x4.trans.shared.b16 {%0,%1,%2,%3}, [%4];"
                 : "=r"(r[0]), "=r"(r[1]), "=r"(r[2]), "=r"(r[3]) : "r"(a));
}

__device__ __forceinline__ void mma_f16(float c[4], const unsigned a[4],
                                        unsigned b0, unsigned b1) {
    asm volatile(
        "mma.sync.aligned.m16n8k16.row.col.f32.f16.f16.f32 "
        "{%0,%1,%2,%3}, {%4,%5,%6,%7}, {%8,%9}, {%0,%1,%2,%3};"
        : "+f"(c[0]), "+f"(c[1]), "+f"(c[2]), "+f"(c[3])
        : "r"(a[0]), "r"(a[1]), "r"(a[2]), "r"(a[3]), "r"(b0), "r"(b1));
}

// ---------------------------------------------------------------------------
__global__ void zero_deg_kernel() {
    int i = blockIdx.x * blockDim.x + threadIdx.x;
    if (i < NN) { g_rowdeg[i] = 0.f; g_coldeg[i] = 0.f; }
}

// ---------------------------------------------------------------------------
// One pass over m: row sums, col sums, and fp16 conversion.
// Block: 256 threads = 512 columns (2 per thread), 512 rows. Grid (16, 16).
__global__ __launch_bounds__(256) void degconv_kernel(const float* __restrict__ m) {
    const int c    = (blockIdx.x * 256 + threadIdx.x) * 2;
    const int r0   = blockIdx.y * 512;
    const int lane = threadIdx.x & 31;
    float ca0 = 0.f, ca1 = 0.f;

    for (int r = r0; r < r0 + 512; r += 8) {
        float2 v[8];
        float  rs[8];
#pragma unroll
        for (int j = 0; j < 8; j++)
            v[j] = *(const float2*)&m[(size_t)(r + j) * NN + c];
#pragma unroll
        for (int j = 0; j < 8; j++) {
            *(__half2*)&g_mh[(size_t)(r + j) * NN + c] =
                __floats2half2_rn(v[j].x, v[j].y);
            ca0 += v[j].x;
            ca1 += v[j].y;
            rs[j] = v[j].x + v[j].y;
        }
#pragma unroll
        for (int j = 0; j < 8; j++) {
            rs[j] += __shfl_xor_sync(0xffffffffu, rs[j], 16);
            rs[j] += __shfl_xor_sync(0xffffffffu, rs[j], 8);
            rs[j] += __shfl_xor_sync(0xffffffffu, rs[j], 4);
            rs[j] += __shfl_xor_sync(0xffffffffu, rs[j], 2);
            rs[j] += __shfl_xor_sync(0xffffffffu, rs[j], 1);
        }
        if (lane == 0) {
#pragma unroll
            for (int j = 0; j < 8; j++)
                atomicAdd(&g_rowdeg[r + j], rs[j]);
        }
    }
    atomicAdd(&g_coldeg[c], ca0);
    atomicAdd(&g_coldeg[c + 1], ca1);
}

// ---------------------------------------------------------------------------
// g_msg = relu(in @ w^T + b) * rsqrt(col_deg[row]) as fp16.
// in = gather(emb, x) (gather=1) or g_h (gather=0).
__global__ __launch_bounds__(256) void linear_kernel(
    const float* __restrict__ ext, const int* __restrict__ idx,
    const float* __restrict__ w, const float* __restrict__ b, int gather) {
    __shared__ float ht[32 * 36];
    __shared__ float wt[32 * 132];

    const int tid  = threadIdx.x;
    const int brow = blockIdx.x * 32;
    const int rg   = tid >> 5;
    const int cg   = tid & 31;

    const int sr  = tid >> 3;
    const int sk4 = (tid & 7) << 2;
    const int node = brow + sr;
    const float* src;
    if (gather) src = ext + (size_t)idx[node] * FDIM;
    else        src = &g_h[(size_t)node * FDIM];

    float acc[4][4];
#pragma unroll
    for (int j = 0; j < 4; j++)
#pragma unroll
        for (int jj = 0; jj < 4; jj++) acc[j][jj] = 0.f;

    for (int kc = 0; kc < 4; kc++) {
        const int k0 = kc * 32;
        if (kc) __syncthreads();

        float4 hv = *(const float4*)(src + k0 + sk4);
        ht[sr * 36 + sk4 + 0] = hv.x;
        ht[sr * 36 + sk4 + 1] = hv.y;
        ht[sr * 36 + sk4 + 2] = hv.z;
        ht[sr * 36 + sk4 + 3] = hv.w;

#pragma unroll
        for (int i = 0; i < 4; i++) {
            int lin4 = tid + i * 256;
            int c    = lin4 >> 3;
            int kk4  = (lin4 & 7) << 2;
            float4 wv = *(const float4*)(w + (size_t)c * FDIM + k0 + kk4);
            wt[(kk4 + 0) * 132 + c] = wv.x;
            wt[(kk4 + 1) * 132 + c] = wv.y;
            wt[(kk4 + 2) * 132 + c] = wv.z;
            wt[(kk4 + 3) * 132 + c] = wv.w;
        }
        __syncthreads();

#pragma unroll
        for (int k = 0; k < 32; k++) {
            float hvv[4], wvv[4];
#pragma unroll
            for (int j = 0; j < 4; j++)  hvv[j]  = ht[(rg * 4 + j) * 36 + k];
#pragma unroll
            for (int jj = 0; jj < 4; jj++) wvv[jj] = wt[k * 132 + cg + 32 * jj];
#pragma unroll
            for (int j = 0; j < 4; j++)
#pragma unroll
                for (int jj = 0; jj < 4; jj++)
                    acc[j][jj] += hvv[j] * wvv[jj];
        }
    }

#pragma unroll
    for (int j = 0; j < 4; j++) {
        const int rr = brow + rg * 4 + j;
        const float sc = rsqrtf(g_coldeg[rr]);
#pragma unroll
        for (int jj = 0; jj < 4; jj++) {
            const int c = cg + 32 * jj;
            float v = acc[j][jj] + b[c];
            v = fmaxf(v, 0.f);
            g_msg[(size_t)rr * FDIM + c] = __float2half_rn(v * sc);
        }
    }
}

// ---------------------------------------------------------------------------
// g_h = rsqrt(row_deg) * (g_mh @ g_msg)   M=8192, N=128, K=8192.
// fp16 HMMA m16n8k16, ldmatrix fragments, cp.async 3-stage ring.
// Block tile 64x128, BK=32, 256 threads = 8 warps (2x4), warp tile 32x32.
__global__ __launch_bounds__(256) void gemm_fp16_kernel() {
    __shared__ __half As[NSTAGE][BM * APAD];   // 3 * 5120 B
    __shared__ __half Bs[NSTAGE][BK * BPAD];   // 3 * 8704 B

    const int tid  = threadIdx.x;
    const int brow = blockIdx.x * BM;
    const int warp = tid >> 5, lane = tid & 31;
    const int wm   = (warp >> 2) * 32;
    const int wn   = (warp & 3) * 32;

    // cp.async staging assignments
    const int ar = tid >> 2, ak = (tid & 3) * 8;         // A: 64 rows x 4 chunks
    const __half* gA = &g_mh[(size_t)(brow + ar) * NN + ak];
    const unsigned sA = smem_u32(&As[0][ar * APAD + ak]);

    const int br0 = tid >> 4, bn = (tid & 15) * 8;       // B: 32 rows x 16 chunks (2 per thread)
    const __half* gB0 = &g_msg[(size_t)br0 * FDIM + bn];
    const unsigned sB0 = smem_u32(&Bs[0][br0 * BPAD + bn]);
    const __half* gB1 = gB0 + 16 * FDIM;
    const unsigned sB1 = sB0 + 16 * BPAD * 2;

    const unsigned ABYTES = BM * APAD * 2;
    const unsigned BBYTES = BK * BPAD * 2;

    // ldmatrix lane addressing
    const int lr  = lane & 15;
    const int lc8 = (lane >> 4) * 8;
    const unsigned aBase = smem_u32(&As[0][(wm + lr) * APAD + lc8]);
    const unsigned bBase = smem_u32(&Bs[0][lr * BPAD + wn + lc8]);

    float acc[2][4][4];
#pragma unroll
    for (int mt = 0; mt < 2; mt++)
#pragma unroll
        for (int nt = 0; nt < 4; nt++)
#pragma unroll
            for (int e = 0; e < 4; e++) acc[mt][nt][e] = 0.f;

    // prefetch NSTAGE-1 tiles
#pragma unroll
    for (int s = 0; s < NSTAGE - 1; s++) {
        cp_async16(sA + s * ABYTES, gA + s * BK);
        cp_async16(sB0 + s * BBYTES, gB0 + (size_t)s * BK * FDIM);
        cp_async16(sB1 + s * BBYTES, gB1 + (size_t)s * BK * FDIM);
        cp_commit();
    }

#pragma unroll 1
    for (int kt = 0; kt < KTILES; kt++) {
        cp_wait<NSTAGE - 2>();
        __syncthreads();

        // issue tile kt+NSTAGE-1 into the buffer freed at iteration kt-1
        const int t = kt + NSTAGE - 1;
        if (t < KTILES) {
            const int s = t % NSTAGE;
            cp_async16(sA + s * ABYTES, gA + t * BK);
            cp_async16(sB0 + s * BBYTES, gB0 + (size_t)t * BK * FDIM);
            cp_async16(sB1 + s * BBYTES, gB1 + (size_t)t * BK * FDIM);
        }
        cp_commit();

        const int st = kt % NSTAGE;
        const unsigned aS = aBase + st * ABYTES;
        const unsigned bS = bBase + st * BBYTES;
#pragma unroll
        for (int kk = 0; kk < BK; kk += 16) {
            unsigned a[2][4], b[2][4];
            ldsm4(a[0], aS + kk * 2);
            ldsm4(a[1], aS + 16 * APAD * 2 + kk * 2);
            ldsm4t(b[0], bS + kk * BPAD * 2);
            ldsm4t(b[1], bS + kk * BPAD * 2 + 32);
#pragma unroll
            for (int mt = 0; mt < 2; mt++)
#pragma unroll
                for (int nt = 0; nt < 4; nt++)
                    mma_f16(acc[mt][nt], a[mt],
                            b[nt >> 1][(nt & 1) * 2], b[nt >> 1][(nt & 1) * 2 + 1]);
        }
    }

    // epilogue: scale by rsqrt(row_deg), store fp32
#pragma unroll
    for (int mt = 0; mt < 2; mt++) {
        const int row = brow + wm + mt * 16 + (lane >> 2);
        const float rs0 = rsqrtf(g_rowdeg[row]);
        const float rs1 = rsqrtf(g_rowdeg[row + 8]);
#pragma unroll
        for (int nt = 0; nt < 4; nt++) {
            const int col = wn + nt * 8 + (lane & 3) * 2;
            const size_t o0 = (size_t)row * FDIM + col;
            g_h[o0]              = acc[mt][nt][0] * rs0;
            g_h[o0 + 1]          = acc[mt][nt][1] * rs0;
            g_h[o0 + 8 * FDIM]     = acc[mt][nt][2] * rs1;
            g_h[o0 + 8 * FDIM + 1] = acc[mt][nt][3] * rs1;
        }
    }
}

// ---------------------------------------------------------------------------
__global__ void pool_classify_kernel(const float* __restrict__ wc,
                                     const float* __restrict__ bc,
                                     float* __restrict__ out) {
    __shared__ float pooled[FDIM];
    const int gidx = blockIdx.x;
    const int c    = threadIdx.x;
    const float* base = &g_h[(size_t)gidx * 128 * FDIM + c];
    float mx = -1e30f;
#pragma unroll 8
    for (int r = 0; r < 128; r++)
        mx = fmaxf(mx, base[(size_t)r * FDIM]);
    pooled[c] = mx;
    __syncthreads();
    if (c < NCLS) {
        float a = bc[c];
#pragma unroll 8
        for (int k = 0; k < FDIM; k++)
            a += pooled[k] * wc[c * FDIM + k];
        out[gidx * NCLS + c] = a;
    }
}

// ---------------------------------------------------------------------------
extern "C" void kernel_launch(void* const* d_in, const int* in_sizes, int n_in,
                              void* d_out, int out_size) {
    const int*   x   = (const int*)d_in[0];
    const float* m   = (const float*)d_in[1];
    // d_in[2] = bm (unused: segments are exactly contiguous 128-row blocks)
    const float* emb = (const float*)d_in[3];
    const float* w1  = (const float*)d_in[4];
    const float* b1  = (const float*)d_in[5];
    const float* w2  = (const float*)d_in[6];
    const float* b2  = (const float*)d_in[7];
    const float* wc  = (const float*)d_in[8];
    const float* bc  = (const float*)d_in[9];
    float* out = (float*)d_out;

    zero_deg_kernel<<<32, 256>>>();
    degconv_kernel<<<dim3(16, 16), 256>>>(m);

    // layer 1
    linear_kernel<<<NN / 32, 256>>>(emb, x, w1, b1, 1);
    gemm_fp16_kernel<<<NN / BM, 256>>>();
    // layer 2
    linear_kernel<<<NN / 32, 256>>>(nullptr, nullptr, w2, b2, 0);
    gemm_fp16_kernel<<<NN / BM, 256>>>();

    pool_classify_kernel<<<NGRAPH, FDIM>>>(wc, bc, out);
}

// round 4
// speedup vs baseline: 2.4609x; 1.2434x over previous
#include <cuda_runtime.h>
#include <cuda_fp16.h>

// ---------------------------------------------------------------------------
// Net_16673063043559: 2-layer dense GCN on GB300 (sm_103a, baseline-PTX only)
//   degconv: row/col sums of m + fp16 conversion (one pass over m)
//   L1:  msg = relu(emb[x] @ w1^T + b1)*csc ; h = rs*(m @ msg)  [split-K=2]
//   L2:  msg = relu((g_h0+g_h1) @ w2^T + b2)*csc ; h = rs*(m @ msg)
//   pool: max over contiguous 128-row blocks of (g_h0+g_h1); @wc^T + bc
// Propagate GEMM: fp16 HMMA m16n8k16 + ldmatrix + cp.async, split-K=2,
// 2 CTAs/SM.
// ---------------------------------------------------------------------------

#define NN     8192
#define FDIM   128
#define NGRAPH 64
#define NCLS   16

// GEMM tiling
#define BM     64
#define BK     32
#define APAD   40     // halves per A smem row (80B stride)
#define BPAD   136    // halves per B smem row (272B stride)
#define NSTAGE 3
#define KSPLIT 2
#define KHALF  (NN / KSPLIT)      // 4096
#define KTILES (KHALF / BK)       // 128

// Scratch (device globals: no allocation allowed)
__device__ __half g_mh[(size_t)NN * NN];   // fp16 copy of m (128 MB)
__device__ __half g_msg[NN * FDIM];        // scaled message (fp16, GEMM B)
__device__ float  g_h0[NN * FDIM];         // split-K partial 0 (rs-scaled)
__device__ float  g_h1[NN * FDIM];         // split-K partial 1 (rs-scaled)
__device__ float  g_rowdeg[NN];
__device__ float  g_coldeg[NN];

// ---------------------------------------------------------------------------
__device__ __forceinline__ unsigned smem_u32(const void* p) {
    return (unsigned)__cvta_generic_to_shared(p);
}
__device__ __forceinline__ void cp_async16(unsigned s, const void* g) {
    asm volatile("cp.async.cg.shared.global [%0], [%1], 16;\n" :: "r"(s), "l"(g));
}
__device__ __forceinline__ void cp_commit() {
    asm volatile("cp.async.commit_group;\n");
}
template <int N>
__device__ __forceinline__ void cp_wait() {
    asm volatile("cp.async.wait_group %0;\n" :: "n"(N));
}
__device__ __forceinline__ void ldsm4(unsigned r[4], unsigned a) {
    asm volatile("ldmatrix.sync.aligned.m8n8.x4.shared.b16 {%0,%1,%2,%3}, [%4];"
                 : "=r"(r[0]), "=r"(r[1]), "=r"(r[2]), "=r"(r[3]) : "r"(a));
}
__device__ __forceinline__ void ldsm4t(unsigned r[4], unsigned a) {
    asm volatile("ldmatrix.sync.aligned.m8n8.x4.trans.shared.b16 {%0,%1,%2,%3}, [%4];"
                 : "=r"(r[0]), "=r"(r[1]), "=r"(r[2]), "=r"(r[3]) : "r"(a));
}
__device__ __forceinline__ void mma_f16(float c[4], const unsigned a[4],
                                        unsigned b0, unsigned b1) {
    asm volatile(
        "mma.sync.aligned.m16n8k16.row.col.f32.f16.f16.f32 "
        "{%0,%1,%2,%3}, {%4,%5,%6,%7}, {%8,%9}, {%0,%1,%2,%3};"
        : "+f"(c[0]), "+f"(c[1]), "+f"(c[2]), "+f"(c[3])
        : "r"(a[0]), "r"(a[1]), "r"(a[2]), "r"(a[3]), "r"(b0), "r"(b1));
}

// ---------------------------------------------------------------------------
__global__ void zero_deg_kernel() {
    int i = blockIdx.x * blockDim.x + threadIdx.x;
    if (i < NN) { g_rowdeg[i] = 0.f; g_coldeg[i] = 0.f; }
}

// ---------------------------------------------------------------------------
// One pass over m: row sums, col sums, fp16 conversion.
// Thread owns 4 consecutive columns (float4 loads, 8B packed half stores).
// Grid (8, 16): block covers 1024 cols x 512 rows.
__global__ __launch_bounds__(256) void degconv_kernel(const float* __restrict__ m) {
    const int c    = (blockIdx.x * 256 + threadIdx.x) * 4;
    const int r0   = blockIdx.y * 512;
    const int lane = threadIdx.x & 31;
    float ca0 = 0.f, ca1 = 0.f, ca2 = 0.f, ca3 = 0.f;

    for (int r = r0; r < r0 + 512; r += 8) {
        float4 v[8];
        float  rs[8];
#pragma unroll
        for (int j = 0; j < 8; j++)
            v[j] = *(const float4*)&m[(size_t)(r + j) * NN + c];
#pragma unroll
        for (int j = 0; j < 8; j++) {
            __half2 h01 = __floats2half2_rn(v[j].x, v[j].y);
            __half2 h23 = __floats2half2_rn(v[j].z, v[j].w);
            *(uint2*)&g_mh[(size_t)(r + j) * NN + c] =
                make_uint2(*(unsigned*)&h01, *(unsigned*)&h23);
            ca0 += v[j].x; ca1 += v[j].y; ca2 += v[j].z; ca3 += v[j].w;
            rs[j] = (v[j].x + v[j].y) + (v[j].z + v[j].w);
        }
#pragma unroll
        for (int j = 0; j < 8; j++) {
            rs[j] += __shfl_xor_sync(0xffffffffu, rs[j], 16);
            rs[j] += __shfl_xor_sync(0xffffffffu, rs[j], 8);
            rs[j] += __shfl_xor_sync(0xffffffffu, rs[j], 4);
            rs[j] += __shfl_xor_sync(0xffffffffu, rs[j], 2);
            rs[j] += __shfl_xor_sync(0xffffffffu, rs[j], 1);
        }
        if (lane == 0) {
#pragma unroll
            for (int j = 0; j < 8; j++)
                atomicAdd(&g_rowdeg[r + j], rs[j]);
        }
    }
    atomicAdd(&g_coldeg[c + 0], ca0);
    atomicAdd(&g_coldeg[c + 1], ca1);
    atomicAdd(&g_coldeg[c + 2], ca2);
    atomicAdd(&g_coldeg[c + 3], ca3);
}

// ---------------------------------------------------------------------------
// g_msg = relu(in @ w^T + b) * rsqrt(col_deg[row]) as fp16.
// in = gather(emb, x) (gather=1) or g_h0+g_h1 (gather=0, rs already applied).
__global__ __launch_bounds__(256) void linear_kernel(
    const float* __restrict__ ext, const int* __restrict__ idx,
    const float* __restrict__ w, const float* __restrict__ b, int gather) {
    __shared__ float ht[32 * 36];
    __shared__ float wt[32 * 132];

    const int tid  = threadIdx.x;
    const int brow = blockIdx.x * 32;
    const int rg   = tid >> 5;
    const int cg   = tid & 31;

    const int sr   = tid >> 3;
    const int sk4  = (tid & 7) << 2;
    const int node = brow + sr;
    const float* src = gather ? (ext + (size_t)idx[node] * FDIM)
                              : (const float*)&g_h0[(size_t)node * FDIM];

    float acc[4][4];
#pragma unroll
    for (int j = 0; j < 4; j++)
#pragma unroll
        for (int jj = 0; jj < 4; jj++) acc[j][jj] = 0.f;

    for (int kc = 0; kc < 4; kc++) {
        const int k0 = kc * 32;
        if (kc) __syncthreads();

        float4 hv = *(const float4*)(src + k0 + sk4);
        if (!gather) {
            float4 h2 = *(const float4*)&g_h1[(size_t)node * FDIM + k0 + sk4];
            hv.x += h2.x; hv.y += h2.y; hv.z += h2.z; hv.w += h2.w;
        }
        ht[sr * 36 + sk4 + 0] = hv.x;
        ht[sr * 36 + sk4 + 1] = hv.y;
        ht[sr * 36 + sk4 + 2] = hv.z;
        ht[sr * 36 + sk4 + 3] = hv.w;

#pragma unroll
        for (int i = 0; i < 4; i++) {
            int lin4 = tid + i * 256;
            int c    = lin4 >> 3;
            int kk4  = (lin4 & 7) << 2;
            float4 wv = *(const float4*)(w + (size_t)c * FDIM + k0 + kk4);
            wt[(kk4 + 0) * 132 + c] = wv.x;
            wt[(kk4 + 1) * 132 + c] = wv.y;
            wt[(kk4 + 2) * 132 + c] = wv.z;
            wt[(kk4 + 3) * 132 + c] = wv.w;
        }
        __syncthreads();

#pragma unroll
        for (int k = 0; k < 32; k++) {
            float hvv[4], wvv[4];
#pragma unroll
            for (int j = 0; j < 4; j++)  hvv[j]  = ht[(rg * 4 + j) * 36 + k];
#pragma unroll
            for (int jj = 0; jj < 4; jj++) wvv[jj] = wt[k * 132 + cg + 32 * jj];
#pragma unroll
            for (int j = 0; j < 4; j++)
#pragma unroll
                for (int jj = 0; jj < 4; jj++)
                    acc[j][jj] += hvv[j] * wvv[jj];
        }
    }

#pragma unroll
    for (int j = 0; j < 4; j++) {
        const int rr = brow + rg * 4 + j;
        const float sc = rsqrtf(g_coldeg[rr]);
#pragma unroll
        for (int jj = 0; jj < 4; jj++) {
            const int c = cg + 32 * jj;
            float v = acc[j][jj] + b[c];
            v = fmaxf(v, 0.f);
            g_msg[(size_t)rr * FDIM + c] = __float2half_rn(v * sc);
        }
    }
}

// ---------------------------------------------------------------------------
// Split-K propagate GEMM: partial = rs * (g_mh[:, Kslice] @ g_msg[Kslice, :]).
// Grid (128, 2): x = M tile (64 rows), y = K half. 2 CTAs/SM.
// fp16 HMMA m16n8k16, ldmatrix fragments, cp.async 3-stage ring.
__global__ void __launch_bounds__(256, 2) gemm_fp16_kernel() {
    __shared__ __half As[NSTAGE][BM * APAD];
    __shared__ __half Bs[NSTAGE][BK * BPAD];

    const int tid  = threadIdx.x;
    const int brow = blockIdx.x * BM;
    const int koff = blockIdx.y * KHALF;
    float* out = blockIdx.y ? g_h1 : g_h0;

    const int warp = tid >> 5, lane = tid & 31;
    const int wm   = (warp >> 2) * 32;
    const int wn   = (warp & 3) * 32;

    // cp.async staging assignments
    const int ar = tid >> 2, ak = (tid & 3) * 8;       // A: 64 rows x 4 chunks
    const __half* gA = &g_mh[(size_t)(brow + ar) * NN + koff + ak];
    const unsigned sA = smem_u32(&As[0][ar * APAD + ak]);

    const int br0 = tid >> 4, bn = (tid & 15) * 8;     // B: 32 rows x 16 chunks
    const __half* gB0 = &g_msg[(size_t)(koff + br0) * FDIM + bn];
    const unsigned sB0 = smem_u32(&Bs[0][br0 * BPAD + bn]);
    const __half* gB1 = gB0 + 16 * FDIM;
    const unsigned sB1 = sB0 + 16 * BPAD * 2;

    const unsigned ABYTES = BM * APAD * 2;
    const unsigned BBYTES = BK * BPAD * 2;

    // ldmatrix lane addressing
    const int lr  = lane & 15;
    const int lc8 = (lane >> 4) * 8;
    const unsigned aBase = smem_u32(&As[0][(wm + lr) * APAD + lc8]);
    const unsigned bBase = smem_u32(&Bs[0][lr * BPAD + wn + lc8]);

    float acc[2][4][4];
#pragma unroll
    for (int mt = 0; mt < 2; mt++)
#pragma unroll
        for (int nt = 0; nt < 4; nt++)
#pragma unroll
            for (int e = 0; e < 4; e++) acc[mt][nt][e] = 0.f;

    // prefetch NSTAGE-1 tiles
#pragma unroll
    for (int s = 0; s < NSTAGE - 1; s++) {
        cp_async16(sA + s * ABYTES, gA + s * BK);
        cp_async16(sB0 + s * BBYTES, gB0 + (size_t)s * BK * FDIM);
        cp_async16(sB1 + s * BBYTES, gB1 + (size_t)s * BK * FDIM);
        cp_commit();
    }

#pragma unroll 1
    for (int kt = 0; kt < KTILES; kt++) {
        cp_wait<NSTAGE - 2>();
        __syncthreads();

        const int t = kt + NSTAGE - 1;
        if (t < KTILES) {
            const int s = t % NSTAGE;
            cp_async16(sA + s * ABYTES, gA + t * BK);
            cp_async16(sB0 + s * BBYTES, gB0 + (size_t)t * BK * FDIM);
            cp_async16(sB1 + s * BBYTES, gB1 + (size_t)t * BK * FDIM);
        }
        cp_commit();

        const int st = kt % NSTAGE;
        const unsigned aS = aBase + st * ABYTES;
        const unsigned bS = bBase + st * BBYTES;
#pragma unroll
        for (int kk = 0; kk < BK; kk += 16) {
            unsigned a[2][4], b[2][4];
            ldsm4(a[0], aS + kk * 2);
            ldsm4(a[1], aS + 16 * APAD * 2 + kk * 2);
            ldsm4t(b[0], bS + kk * BPAD * 2);
            ldsm4t(b[1], bS + kk * BPAD * 2 + 32);
#pragma unroll
            for (int mt = 0; mt < 2; mt++)
#pragma unroll
                for (int nt = 0; nt < 4; nt++)
                    mma_f16(acc[mt][nt], a[mt],
                            b[nt >> 1][(nt & 1) * 2], b[nt >> 1][(nt & 1) * 2 + 1]);
        }
    }

    // epilogue: scale by rsqrt(row_deg), store fp32 partial
#pragma unroll
    for (int mt = 0; mt < 2; mt++) {
        const int row = brow + wm + mt * 16 + (lane >> 2);
        const float rs0 = rsqrtf(g_rowdeg[row]);
        const float rs1 = rsqrtf(g_rowdeg[row + 8]);
#pragma unroll
        for (int nt = 0; nt < 4; nt++) {
            const int col = wn + nt * 8 + (lane & 3) * 2;
            const size_t o0 = (size_t)row * FDIM + col;
            out[o0]                = acc[mt][nt][0] * rs0;
            out[o0 + 1]            = acc[mt][nt][1] * rs0;
            out[o0 + 8 * FDIM]     = acc[mt][nt][2] * rs1;
            out[o0 + 8 * FDIM + 1] = acc[mt][nt][3] * rs1;
        }
    }
}

// ---------------------------------------------------------------------------
// pooled[g] = max over 128 rows of (g_h0+g_h1); logits = pooled @ wc^T + bc
__global__ void pool_classify_kernel(const float* __restrict__ wc,
                                     const float* __restrict__ bc,
                                     float* __restrict__ out) {
    __shared__ float pooled[FDIM];
    const int gidx = blockIdx.x;
    const int c    = threadIdx.x;
    const size_t base = (size_t)gidx * 128 * FDIM + c;
    float mx = -1e30f;
#pragma unroll 8
    for (int r = 0; r < 128; r++) {
        const size_t o = base + (size_t)r * FDIM;
        mx = fmaxf(mx, g_h0[o] + g_h1[o]);
    }
    pooled[c] = mx;
    __syncthreads();
    if (c < NCLS) {
        float a = bc[c];
#pragma unroll 8
        for (int k = 0; k < FDIM; k++)
            a += pooled[k] * wc[c * FDIM + k];
        out[gidx * NCLS + c] = a;
    }
}

// ---------------------------------------------------------------------------
extern "C" void kernel_launch(void* const* d_in, const int* in_sizes, int n_in,
                              void* d_out, int out_size) {
    const int*   x   = (const int*)d_in[0];
    const float* m   = (const float*)d_in[1];
    // d_in[2] = bm (unused: segments are exactly contiguous 128-row blocks)
    const float* emb = (const float*)d_in[3];
    const float* w1  = (const float*)d_in[4];
    const float* b1  = (const float*)d_in[5];
    const float* w2  = (const float*)d_in[6];
    const float* b2  = (const float*)d_in[7];
    const float* wc  = (const float*)d_in[8];
    const float* bc  = (const float*)d_in[9];
    float* out = (float*)d_out;

    zero_deg_kernel<<<32, 256>>>();
    degconv_kernel<<<dim3(8, 16), 256>>>(m);

    // layer 1
    linear_kernel<<<NN / 32, 256>>>(emb, x, w1, b1, 1);
    gemm_fp16_kernel<<<dim3(NN / BM, KSPLIT), 256>>>();
    // layer 2
    linear_kernel<<<NN / 32, 256>>>(nullptr, nullptr, w2, b2, 0);
    gemm_fp16_kernel<<<dim3(NN / BM, KSPLIT), 256>>>();

    pool_classify_kernel<<<NGRAPH, FDIM>>>(wc, bc, out);
}

// round 5
// speedup vs baseline: 2.8069x; 1.1406x over previous
#include <cuda_runtime.h>
#include <cuda_fp16.h>

// ---------------------------------------------------------------------------
// Net_16673063043559: 2-layer dense GCN on GB300 (sm_103a, baseline-PTX only)
//   degconv: row/col sums of m + fp16 conversion (one pass over m)
//   L1:  msg = relu(emb[x] @ w1^T + b1)*csc ; h = rs*(m @ msg)  [split-K=2]
//   L2:  msg = relu((g_h0+g_h1) @ w2^T + b2)*csc ; h = rs*(m @ msg)
//   pool: max over contiguous 128-row blocks of (g_h0+g_h1); @wc^T + bc
// Propagate GEMM: fp16 HMMA m16n8k16 + ldmatrix + cp.async, split-K=2,
// 3 CTAs/SM.
// ---------------------------------------------------------------------------

#define NN     8192
#define FDIM   128
#define NGRAPH 64
#define NCLS   16

// GEMM tiling
#define BM     64
#define BK     32
#define APAD   40     // halves per A smem row (80B stride)
#define BPAD   136    // halves per B smem row (272B stride)
#define NSTAGE 3
#define KSPLIT 2
#define KHALF  (NN / KSPLIT)      // 4096
#define KTILES (KHALF / BK)       // 128

// Scratch (device globals: no allocation allowed)
__device__ __half g_mh[(size_t)NN * NN];   // fp16 copy of m (128 MB)
__device__ __half g_msg[NN * FDIM];        // scaled message (fp16, GEMM B)
__device__ float  g_h0[NN * FDIM];         // split-K partial 0 (rs-scaled)
__device__ float  g_h1[NN * FDIM];         // split-K partial 1 (rs-scaled)
__device__ float  g_rowdeg[NN];
__device__ float  g_coldeg[NN];

// ---------------------------------------------------------------------------
__device__ __forceinline__ unsigned smem_u32(const void* p) {
    return (unsigned)__cvta_generic_to_shared(p);
}
__device__ __forceinline__ void cp_async16(unsigned s, const void* g) {
    asm volatile("cp.async.cg.shared.global [%0], [%1], 16;\n" :: "r"(s), "l"(g));
}
__device__ __forceinline__ void cp_commit() {
    asm volatile("cp.async.commit_group;\n");
}
template <int N>
__device__ __forceinline__ void cp_wait() {
    asm volatile("cp.async.wait_group %0;\n" :: "n"(N));
}
__device__ __forceinline__ void ldsm4(unsigned r[4], unsigned a) {
    asm volatile("ldmatrix.sync.aligned.m8n8.x4.shared.b16 {%0,%1,%2,%3}, [%4];"
                 : "=r"(r[0]), "=r"(r[1]), "=r"(r[2]), "=r"(r[3]) : "r"(a));
}
__device__ __forceinline__ void ldsm4t(unsigned r[4], unsigned a) {
    asm volatile("ldmatrix.sync.aligned.m8n8.x4.trans.shared.b16 {%0,%1,%2,%3}, [%4];"
                 : "=r"(r[0]), "=r"(r[1]), "=r"(r[2]), "=r"(r[3]) : "r"(a));
}
__device__ __forceinline__ void mma_f16(float c[4], const unsigned a[4],
                                        unsigned b0, unsigned b1) {
    asm volatile(
        "mma.sync.aligned.m16n8k16.row.col.f32.f16.f16.f32 "
        "{%0,%1,%2,%3}, {%4,%5,%6,%7}, {%8,%9}, {%0,%1,%2,%3};"
        : "+f"(c[0]), "+f"(c[1]), "+f"(c[2]), "+f"(c[3])
        : "r"(a[0]), "r"(a[1]), "r"(a[2]), "r"(a[3]), "r"(b0), "r"(b1));
}

// ---------------------------------------------------------------------------
__global__ void zero_deg_kernel() {
    int i = blockIdx.x * blockDim.x + threadIdx.x;
    if (i < NN) { g_rowdeg[i] = 0.f; g_coldeg[i] = 0.f; }
}

// ---------------------------------------------------------------------------
// One pass over m: row sums, col sums, fp16 conversion.
// Thread owns 4 consecutive columns (float4 loads, 8B packed half stores).
// Grid (8, 32): block covers 1024 cols x 256 rows -> 256 CTAs.
__global__ __launch_bounds__(256) void degconv_kernel(const float* __restrict__ m) {
    const int c    = (blockIdx.x * 256 + threadIdx.x) * 4;
    const int r0   = blockIdx.y * 256;
    const int lane = threadIdx.x & 31;
    float ca0 = 0.f, ca1 = 0.f, ca2 = 0.f, ca3 = 0.f;

    for (int r = r0; r < r0 + 256; r += 8) {
        float4 v[8];
        float  rs[8];
#pragma unroll
        for (int j = 0; j < 8; j++)
            v[j] = *(const float4*)&m[(size_t)(r + j) * NN + c];
#pragma unroll
        for (int j = 0; j < 8; j++) {
            __half2 h01 = __floats2half2_rn(v[j].x, v[j].y);
            __half2 h23 = __floats2half2_rn(v[j].z, v[j].w);
            *(uint2*)&g_mh[(size_t)(r + j) * NN + c] =
                make_uint2(*(unsigned*)&h01, *(unsigned*)&h23);
            ca0 += v[j].x; ca1 += v[j].y; ca2 += v[j].z; ca3 += v[j].w;
            rs[j] = (v[j].x + v[j].y) + (v[j].z + v[j].w);
        }
#pragma unroll
        for (int j = 0; j < 8; j++) {
            rs[j] += __shfl_xor_sync(0xffffffffu, rs[j], 16);
            rs[j] += __shfl_xor_sync(0xffffffffu, rs[j], 8);
            rs[j] += __shfl_xor_sync(0xffffffffu, rs[j], 4);
            rs[j] += __shfl_xor_sync(0xffffffffu, rs[j], 2);
            rs[j] += __shfl_xor_sync(0xffffffffu, rs[j], 1);
        }
        if (lane == 0) {
#pragma unroll
            for (int j = 0; j < 8; j++)
                atomicAdd(&g_rowdeg[r + j], rs[j]);
        }
    }
    atomicAdd(&g_coldeg[c + 0], ca0);
    atomicAdd(&g_coldeg[c + 1], ca1);
    atomicAdd(&g_coldeg[c + 2], ca2);
    atomicAdd(&g_coldeg[c + 3], ca3);
}

// ---------------------------------------------------------------------------
// g_msg = relu(in @ w^T + b) * rsqrt(col_deg[row]) as fp16.
// in = gather(emb, x) (gather=1) or g_h0+g_h1 (gather=0, rs already applied).
__global__ __launch_bounds__(256) void linear_kernel(
    const float* __restrict__ ext, const int* __restrict__ idx,
    const float* __restrict__ w, const float* __restrict__ b, int gather) {
    __shared__ float ht[32 * 36];
    __shared__ float wt[32 * 132];

    const int tid  = threadIdx.x;
    const int brow = blockIdx.x * 32;
    const int rg   = tid >> 5;
    const int cg   = tid & 31;

    const int sr   = tid >> 3;
    const int sk4  = (tid & 7) << 2;
    const int node = brow + sr;
    const float* src = gather ? (ext + (size_t)idx[node] * FDIM)
                              : (const float*)&g_h0[(size_t)node * FDIM];

    float acc[4][4];
#pragma unroll
    for (int j = 0; j < 4; j++)
#pragma unroll
        for (int jj = 0; jj < 4; jj++) acc[j][jj] = 0.f;

    for (int kc = 0; kc < 4; kc++) {
        const int k0 = kc * 32;
        if (kc) __syncthreads();

        float4 hv = *(const float4*)(src + k0 + sk4);
        if (!gather) {
            float4 h2 = *(const float4*)&g_h1[(size_t)node * FDIM + k0 + sk4];
            hv.x += h2.x; hv.y += h2.y; hv.z += h2.z; hv.w += h2.w;
        }
        ht[sr * 36 + sk4 + 0] = hv.x;
        ht[sr * 36 + sk4 + 1] = hv.y;
        ht[sr * 36 + sk4 + 2] = hv.z;
        ht[sr * 36 + sk4 + 3] = hv.w;

#pragma unroll
        for (int i = 0; i < 4; i++) {
            int lin4 = tid + i * 256;
            int c    = lin4 >> 3;
            int kk4  = (lin4 & 7) << 2;
            float4 wv = *(const float4*)(w + (size_t)c * FDIM + k0 + kk4);
            wt[(kk4 + 0) * 132 + c] = wv.x;
            wt[(kk4 + 1) * 132 + c] = wv.y;
            wt[(kk4 + 2) * 132 + c] = wv.z;
            wt[(kk4 + 3) * 132 + c] = wv.w;
        }
        __syncthreads();

#pragma unroll
        for (int k = 0; k < 32; k++) {
            float hvv[4], wvv[4];
#pragma unroll
            for (int j = 0; j < 4; j++)  hvv[j]  = ht[(rg * 4 + j) * 36 + k];
#pragma unroll
            for (int jj = 0; jj < 4; jj++) wvv[jj] = wt[k * 132 + cg + 32 * jj];
#pragma unroll
            for (int j = 0; j < 4; j++)
#pragma unroll
                for (int jj = 0; jj < 4; jj++)
                    acc[j][jj] += hvv[j] * wvv[jj];
        }
    }

#pragma unroll
    for (int j = 0; j < 4; j++) {
        const int rr = brow + rg * 4 + j;
        const float sc = rsqrtf(g_coldeg[rr]);
#pragma unroll
        for (int jj = 0; jj < 4; jj++) {
            const int c = cg + 32 * jj;
            float v = acc[j][jj] + b[c];
            v = fmaxf(v, 0.f);
            g_msg[(size_t)rr * FDIM + c] = __float2half_rn(v * sc);
        }
    }
}

// ---------------------------------------------------------------------------
// Split-K propagate GEMM: partial = rs * (g_mh[:, Kslice] @ g_msg[Kslice, :]).
// Grid (128, 2): x = M tile (64 rows), y = K half. 3 CTAs/SM.
// fp16 HMMA m16n8k16, ldmatrix fragments, cp.async 3-stage ring.
__global__ void __launch_bounds__(256, 3) gemm_fp16_kernel() {
    __shared__ __half As[NSTAGE][BM * APAD];
    __shared__ __half Bs[NSTAGE][BK * BPAD];

    const int tid  = threadIdx.x;
    const int brow = blockIdx.x * BM;
    const int koff = blockIdx.y * KHALF;
    float* out = blockIdx.y ? g_h1 : g_h0;

    const int warp = tid >> 5, lane = tid & 31;
    const int wm   = (warp >> 2) * 32;
    const int wn   = (warp & 3) * 32;

    // cp.async staging assignments
    const int ar = tid >> 2, ak = (tid & 3) * 8;       // A: 64 rows x 4 chunks
    const __half* gA = &g_mh[(size_t)(brow + ar) * NN + koff + ak];
    const unsigned sA = smem_u32(&As[0][ar * APAD + ak]);

    const int br0 = tid >> 4, bn = (tid & 15) * 8;     // B: 32 rows x 16 chunks
    const __half* gB0 = &g_msg[(size_t)(koff + br0) * FDIM + bn];
    const unsigned sB0 = smem_u32(&Bs[0][br0 * BPAD + bn]);
    const __half* gB1 = gB0 + 16 * FDIM;
    const unsigned sB1 = sB0 + 16 * BPAD * 2;

    const unsigned ABYTES = BM * APAD * 2;
    const unsigned BBYTES = BK * BPAD * 2;

    // ldmatrix lane addressing
    const int lr  = lane & 15;
    const int lc8 = (lane >> 4) * 8;
    const unsigned aBase = smem_u32(&As[0][(wm + lr) * APAD + lc8]);
    const unsigned bBase = smem_u32(&Bs[0][lr * BPAD + wn + lc8]);

    float acc[2][4][4];
#pragma unroll
    for (int mt = 0; mt < 2; mt++)
#pragma unroll
        for (int nt = 0; nt < 4; nt++)
#pragma unroll
            for (int e = 0; e < 4; e++) acc[mt][nt][e] = 0.f;

    // prefetch NSTAGE-1 tiles
#pragma unroll
    for (int s = 0; s < NSTAGE - 1; s++) {
        cp_async16(sA + s * ABYTES, gA + s * BK);
        cp_async16(sB0 + s * BBYTES, gB0 + (size_t)s * BK * FDIM);
        cp_async16(sB1 + s * BBYTES, gB1 + (size_t)s * BK * FDIM);
        cp_commit();
    }

#pragma unroll 1
    for (int kt = 0; kt < KTILES; kt++) {
        cp_wait<NSTAGE - 2>();
        __syncthreads();

        const int t = kt + NSTAGE - 1;
        if (t < KTILES) {
            const int s = t % NSTAGE;
            cp_async16(sA + s * ABYTES, gA + t * BK);
            cp_async16(sB0 + s * BBYTES, gB0 + (size_t)t * BK * FDIM);
            cp_async16(sB1 + s * BBYTES, gB1 + (size_t)t * BK * FDIM);
        }
        cp_commit();

        const int st = kt % NSTAGE;
        const unsigned aS = aBase + st * ABYTES;
        const unsigned bS = bBase + st * BBYTES;
#pragma unroll
        for (int kk = 0; kk < BK; kk += 16) {
            unsigned a[2][4], b[2][4];
            ldsm4(a[0], aS + kk * 2);
            ldsm4(a[1], aS + 16 * APAD * 2 + kk * 2);
            ldsm4t(b[0], bS + kk * BPAD * 2);
            ldsm4t(b[1], bS + kk * BPAD * 2 + 32);
#pragma unroll
            for (int mt = 0; mt < 2; mt++)
#pragma unroll
                for (int nt = 0; nt < 4; nt++)
                    mma_f16(acc[mt][nt], a[mt],
                            b[nt >> 1][(nt & 1) * 2], b[nt >> 1][(nt & 1) * 2 + 1]);
        }
    }

    // epilogue: scale by rsqrt(row_deg), store fp32 partial
#pragma unroll
    for (int mt = 0; mt < 2; mt++) {
        const int row = brow + wm + mt * 16 + (lane >> 2);
        const float rs0 = rsqrtf(g_rowdeg[row]);
        const float rs1 = rsqrtf(g_rowdeg[row + 8]);
#pragma unroll
        for (int nt = 0; nt < 4; nt++) {
            const int col = wn + nt * 8 + (lane & 3) * 2;
            const size_t o0 = (size_t)row * FDIM + col;
            out[o0]                = acc[mt][nt][0] * rs0;
            out[o0 + 1]            = acc[mt][nt][1] * rs0;
            out[o0 + 8 * FDIM]     = acc[mt][nt][2] * rs1;
            out[o0 + 8 * FDIM + 1] = acc[mt][nt][3] * rs1;
        }
    }
}

// ---------------------------------------------------------------------------
// pooled[g] = max over 128 rows of (g_h0+g_h1); logits = pooled @ wc^T + bc
__global__ void pool_classify_kernel(const float* __restrict__ wc,
                                     const float* __restrict__ bc,
                                     float* __restrict__ out) {
    __shared__ float pooled[FDIM];
    const int gidx = blockIdx.x;
    const int c    = threadIdx.x;
    const size_t base = (size_t)gidx * 128 * FDIM + c;
    float mx = -1e30f;
#pragma unroll 8
    for (int r = 0; r < 128; r++) {
        const size_t o = base + (size_t)r * FDIM;
        mx = fmaxf(mx, g_h0[o] + g_h1[o]);
    }
    pooled[c] = mx;
    __syncthreads();
    if (c < NCLS) {
        float a = bc[c];
#pragma unroll 8
        for (int k = 0; k < FDIM; k++)
            a += pooled[k] * wc[c * FDIM + k];
        out[gidx * NCLS + c] = a;
    }
}

// ---------------------------------------------------------------------------
extern "C" void kernel_launch(void* const* d_in, const int* in_sizes, int n_in,
                              void* d_out, int out_size) {
    const int*   x   = (const int*)d_in[0];
    const float* m   = (const float*)d_in[1];
    // d_in[2] = bm (unused: segments are exactly contiguous 128-row blocks)
    const float* emb = (const float*)d_in[3];
    const float* w1  = (const float*)d_in[4];
    const float* b1  = (const float*)d_in[5];
    const float* w2  = (const float*)d_in[6];
    const float* b2  = (const float*)d_in[7];
    const float* wc  = (const float*)d_in[8];
    const float* bc  = (const float*)d_in[9];
    float* out = (float*)d_out;

    zero_deg_kernel<<<32, 256>>>();
    degconv_kernel<<<dim3(8, 32), 256>>>(m);

    // layer 1
    linear_kernel<<<NN / 32, 256>>>(emb, x, w1, b1, 1);
    gemm_fp16_kernel<<<dim3(NN / BM, KSPLIT), 256>>>();
    // layer 2
    linear_kernel<<<NN / 32, 256>>>(nullptr, nullptr, w2, b2, 0);
    gemm_fp16_kernel<<<dim3(NN / BM, KSPLIT), 256>>>();

    pool_classify_kernel<<<NGRAPH, FDIM>>>(wc, bc, out);
}